// round 10
// baseline (speedup 1.0000x reference)
#include <cuda_runtime.h>
#include <cstdint>

// ---------------- problem constants ----------------
#define BATCH    128
#define SEQLEN   16384
#define NBANDS   20
#define TAPS     513
#define PAD      512
#define EXTLEN   (SEQLEN + 2*PAD)            // 17408

// ---------------- FFT / overlap-save config ----------------
#define NFFT     4096
#define SEGSTEP  3072
#define NSEG     6
#define NPAIR    ((BATCH/2)*NSEG)            // 384
#define EXTSTRIDE ((NSEG-1)*SEGSTEP + NFFT)  // 19456
#define NT       256
#define BGRP     5                           // bands per inverse work unit
#define NUNITS   ((NBANDS/BGRP)*(BATCH/2)*NSEG)  // 1536
#define PCTAS    (148*3)                     // 444 persistent CTAs

// smem: X[4096] Z[4096] T1[256] Ta[256] float2 = 68 KB
#define SH_BYTES ((4096*2 + 512) * 8)        // 69632

// ---------------- device scratch ----------------
__device__ float  g_ext[BATCH * EXTSTRIDE];
__device__ float2 g_spec[NPAIR * NFFT];
__device__ float  g_H[NBANDS * NFFT];
__device__ float  g_c[NBANDS * TAPS];
__device__ float2 g_T1[256];                 // W_4096^(16*t*r), [t*16+r]
__device__ float2 g_Ta[256];                 // W_4096^(t*r),    [t*16+r]

__device__ __forceinline__ int swz(int i) { return i ^ ((i >> 4) & 15); }

__device__ __forceinline__ float2 cmul(float2 a, float2 b) {
    return make_float2(fmaf(a.x, b.x, -a.y * b.y), fmaf(a.x, b.y, a.y * b.x));
}
template <bool INV>
__device__ __forceinline__ float2 cmulc(float2 a, float cx, float cy) {
    if (INV) cy = -cy;
    return make_float2(fmaf(a.x, cx, -a.y * cy), fmaf(a.x, cy, a.y * cx));
}

template <bool INV>
__device__ __forceinline__ void dft4(float2& x0, float2& x1, float2& x2, float2& x3) {
    float2 t0 = make_float2(x0.x + x2.x, x0.y + x2.y);
    float2 t1 = make_float2(x0.x - x2.x, x0.y - x2.y);
    float2 t2 = make_float2(x1.x + x3.x, x1.y + x3.y);
    float2 t3 = make_float2(x1.x - x3.x, x1.y - x3.y);
    x0 = make_float2(t0.x + t2.x, t0.y + t2.y);
    x2 = make_float2(t0.x - t2.x, t0.y - t2.y);
    if (!INV) {
        x1 = make_float2(t1.x + t3.y, t1.y - t3.x);
        x3 = make_float2(t1.x - t3.y, t1.y + t3.x);
    } else {
        x1 = make_float2(t1.x - t3.y, t1.y + t3.x);
        x3 = make_float2(t1.x + t3.y, t1.y - t3.x);
    }
}

#define W1X  0.92387953251128674f
#define W1Y -0.38268343236508978f
#define W2X  0.70710678118654752f
#define W2Y -0.70710678118654752f
#define W3X  0.38268343236508978f
#define W3Y -0.92387953251128674f
#define W6X -0.70710678118654752f
#define W6Y -0.70710678118654752f
#define W9X -0.92387953251128674f
#define W9Y  0.38268343236508978f

template <bool INV>
__device__ __forceinline__ void dft16(float2* a) {
    #pragma unroll
    for (int n0 = 0; n0 < 4; n0++)
        dft4<INV>(a[n0], a[n0 + 4], a[n0 + 8], a[n0 + 12]);
    a[5]  = cmulc<INV>(a[5],  W1X, W1Y);
    a[9]  = cmulc<INV>(a[9],  W2X, W2Y);
    a[13] = cmulc<INV>(a[13], W3X, W3Y);
    a[6]  = cmulc<INV>(a[6],  W2X, W2Y);
    a[10] = INV ? make_float2(-a[10].y, a[10].x) : make_float2(a[10].y, -a[10].x);
    a[14] = cmulc<INV>(a[14], W6X, W6Y);
    a[7]  = cmulc<INV>(a[7],  W3X, W3Y);
    a[11] = cmulc<INV>(a[11], W6X, W6Y);
    a[15] = cmulc<INV>(a[15], W9X, W9Y);
    #pragma unroll
    for (int k0 = 0; k0 < 4; k0++)
        dft4<INV>(a[4 * k0], a[4 * k0 + 1], a[4 * k0 + 2], a[4 * k0 + 3]);
}
#define PERM(t) ((((t) & 3) << 2) | ((t) >> 2))

// ---------------------------------------------------------------------------
// In-place FFT-4096 using ONE 4096-float2 scratch buffer X.
// Input  a[t] = x[tid + t*256] (registers); output x[tid+t*256] = a[PERM(t)].
// Trailing barrier frees X for the caller's next use.
// ---------------------------------------------------------------------------
template <bool INV>
__device__ __forceinline__ void fft_ip(float2* a, float2* X,
                                       const float2* T1, const float2* Ta, int tid) {
    const int rlo = tid & 15, rhi = tid >> 4;
    // stage 0 (L=1)
    dft16<INV>(a);
    #pragma unroll
    for (int t = 0; t < 16; t++) X[swz(tid * 16 + t)] = a[PERM(t)];
    __syncthreads();
    // stage 1 (L=16): read, barrier, write in place
    #pragma unroll
    for (int t = 0; t < 16; t++) a[t] = X[swz(tid + t * 256)];
    __syncthreads();
    #pragma unroll
    for (int t = 1; t < 16; t++) {
        float2 w = T1[t * 16 + rlo];
        if (INV) w.y = -w.y;
        a[t] = cmul(a[t], w);
    }
    dft16<INV>(a);
    {
        int o = rhi * 256 + rlo;
        #pragma unroll
        for (int t = 0; t < 16; t++) X[swz(o + t * 16)] = a[PERM(t)];
    }
    __syncthreads();
    // stage 2 (L=256): twiddle W^(t*tid) = Ta[t,rlo] * T1[t,rhi]
    #pragma unroll
    for (int t = 0; t < 16; t++) a[t] = X[swz(tid + t * 256)];
    __syncthreads();            // X free for next item
    #pragma unroll
    for (int t = 1; t < 16; t++) {
        float2 wa = Ta[t * 16 + rlo];
        float2 wb = T1[t * 16 + rhi];
        if (INV) { wa.y = -wa.y; wb.y = -wb.y; }
        a[t] = cmul(a[t], cmul(wa, wb));
    }
    dft16<INV>(a);
}

__device__ __forceinline__ void load_tables(float2* T1, float2* Ta, int tid) {
    T1[tid] = g_T1[tid];
    Ta[tid] = g_Ta[tid];
}

// ---------------------------------------------------------------------------
// setup kernels
// ---------------------------------------------------------------------------
__global__ void setup_kernel() {
    int i = threadIdx.x;
    int t = i >> 4, r = i & 15;
    float s_, c_;
    sincospif(2.0f * (float)(16 * t * r) / (float)NFFT, &s_, &c_);
    g_T1[i] = make_float2(c_, -s_);
    sincospif(2.0f * (float)(t * r) / (float)NFFT, &s_, &c_);
    g_Ta[i] = make_float2(c_, -s_);
}

__global__ void build_ext_kernel(const float* __restrict__ x) {
    int idx = blockIdx.x * blockDim.x + threadIdx.x;
    if (idx >= BATCH * EXTSTRIDE) return;
    int b = idx / EXTSTRIDE;
    int j = idx - b * EXTSTRIDE;
    const float* xb = x + b * SEQLEN;
    float v;
    if (j < PAD)               v = 2.0f * xb[0] - xb[PAD - j];
    else if (j < PAD + SEQLEN) v = xb[j - PAD];
    else if (j < EXTLEN) {
        int jr = j - (PAD + SEQLEN);
        v = 2.0f * xb[SEQLEN - 1] - xb[SEQLEN - 2 - jr];
    } else                     v = 0.0f;
    g_ext[idx] = v;
}

__global__ void autocorr_kernel(const float* __restrict__ kern) {
    int band = blockIdx.x;
    const float* kb = kern + band * TAPS;
    __shared__ float sk[TAPS];
    __shared__ int s_last;
    int tid = threadIdx.x;
    for (int i = tid; i < TAPS; i += blockDim.x) sk[i] = kb[i];
    if (tid == 0) s_last = 0;
    __syncthreads();
    if (tid == 0) {
        int last = 0;
        for (int i = 0; i < TAPS; i++) if (sk[i] != 0.0f) last = i;
        s_last = last;
    }
    __syncthreads();
    int M = s_last;
    for (int m = tid; m < TAPS; m += blockDim.x) {
        float s = 0.0f;
        if (m <= M) {
            int jmax = M - m;
            for (int j = 0; j <= jmax; j++) s = fmaf(sk[j], sk[j + m], s);
        }
        g_c[band * TAPS + m] = s;
    }
}

// H[band][f] = Re FFT(wrapped symmetric autocorr) / N
__global__ __launch_bounds__(NT, 3) void h_kernel() {
    extern __shared__ float2 sm[];
    float2* X = sm; float2* T1 = sm + 8192; float2* Ta = sm + 8448;
    int band = blockIdx.x, tid = threadIdx.x;
    load_tables(T1, Ta, tid);
    __syncthreads();
    const float* cb = g_c + band * TAPS;
    float2 a[16];
    #pragma unroll
    for (int t = 0; t < 16; t++) {
        int j = tid + t * 256;
        float v = 0.0f;
        if (j <= PAD)             v = cb[j];
        else if (j >= NFFT - PAD) v = cb[NFFT - j];
        a[t] = make_float2(v, 0.0f);
    }
    fft_ip<false>(a, X, T1, Ta, tid);
    const float invn = 1.0f / (float)NFFT;
    #pragma unroll
    for (int t = 0; t < 16; t++)
        g_H[band * NFFT + tid + t * 256] = a[PERM(t)].x * invn;
}

// forward: z = ext[2bp] + i*ext[2bp+1], one segment per CTA
__global__ __launch_bounds__(NT, 3) void fwd_kernel() {
    extern __shared__ float2 sm[];
    float2* X = sm; float2* T1 = sm + 8192; float2* Ta = sm + 8448;
    int s = blockIdx.x, bp = blockIdx.y, tid = threadIdx.x;
    load_tables(T1, Ta, tid);
    __syncthreads();
    const float* ea = g_ext + (size_t)(2 * bp) * EXTSTRIDE + s * SEGSTEP;
    const float* eb = ea + EXTSTRIDE;
    float2 a[16];
    #pragma unroll
    for (int t = 0; t < 16; t++) {
        int j = tid + t * 256;
        a[t] = make_float2(ea[j], eb[j]);
    }
    fft_ip<false>(a, X, T1, Ta, tid);
    float2* sp = g_spec + (size_t)(bp * NSEG + s) * NFFT;
    #pragma unroll
    for (int t = 0; t < 16; t++)
        sp[tid + t * 256] = a[PERM(t)];
}

// ---------------------------------------------------------------------------
// inverse: persistent CTAs over units (bandgroup, bp, s).
// Z loaded to smem ONCE per unit; each band reads Z from smem + H from L2.
// ---------------------------------------------------------------------------
__global__ __launch_bounds__(NT, 3) void inv_kernel(float* __restrict__ out) {
    extern __shared__ float2 sm[];
    float2* X = sm; float2* Z = sm + 4096; float2* T1 = sm + 8192; float2* Ta = sm + 8448;
    int tid = threadIdx.x;
    load_tables(T1, Ta, tid);
    __syncthreads();
    for (int unit = blockIdx.x; unit < NUNITS; unit += PCTAS) {
        int g   = unit / (NSEG * (BATCH / 2));
        int rem = unit - g * NSEG * (BATCH / 2);
        int bp  = rem / NSEG;
        int s   = rem - bp * NSEG;
        const float2* sp = g_spec + (size_t)(bp * NSEG + s) * NFFT;
        // Z -> smem (coalesced read, swizzled store)
        #pragma unroll
        for (int t = 0; t < 16; t++) {
            int j = tid + t * 256;
            Z[swz(j)] = sp[j];
        }
        __syncthreads();

        size_t basea0 = ((size_t)(2 * bp) * NBANDS) * SEQLEN;
        int pos0 = s * SEGSTEP - PAD + tid;

        #pragma unroll 1
        for (int bi = 0; bi < BGRP; bi++) {
            int band = g * BGRP + bi;
            const float* Hb = g_H + (size_t)band * NFFT;
            float h[16];
            #pragma unroll
            for (int t = 0; t < 16; t++) h[t] = Hb[tid + t * 256];   // LDG burst
            float2 a[16];
            #pragma unroll
            for (int t = 0; t < 16; t++) {
                float2 z = Z[swz(tid + t * 256)];
                a[t] = make_float2(z.x * h[t], z.y * h[t]);
            }
            fft_ip<true>(a, X, T1, Ta, tid);
            // output: j = tid + t*256, valid t = 2..13
            size_t basea = basea0 + (size_t)band * SEQLEN;
            size_t baseb = basea + (size_t)NBANDS * SEQLEN;
            #pragma unroll
            for (int t = 2; t <= 13; t++) {
                int pos = pos0 + t * 256;
                if (pos < SEQLEN) {
                    float2 y = a[PERM(t)];
                    out[basea + pos] = y.x;
                    out[baseb + pos] = y.y;
                }
            }
        }
        __syncthreads();   // all Z reads done before next unit overwrites Z
    }
}

// ---------------------------------------------------------------------------
extern "C" void kernel_launch(void* const* d_in, const int* in_sizes, int n_in,
                              void* d_out, int out_size) {
    (void)in_sizes; (void)n_in; (void)out_size;
    const float* x    = (const float*)d_in[0];
    const float* kern = (const float*)d_in[1];
    float* out = (float*)d_out;

    cudaFuncSetAttribute(h_kernel,   cudaFuncAttributeMaxDynamicSharedMemorySize, SH_BYTES);
    cudaFuncSetAttribute(fwd_kernel, cudaFuncAttributeMaxDynamicSharedMemorySize, SH_BYTES);
    cudaFuncSetAttribute(inv_kernel, cudaFuncAttributeMaxDynamicSharedMemorySize, SH_BYTES);

    setup_kernel<<<1, 256>>>();
    build_ext_kernel<<<(BATCH * EXTSTRIDE + 255) / 256, 256>>>(x);
    autocorr_kernel<<<NBANDS, 256>>>(kern);
    h_kernel<<<NBANDS, NT, SH_BYTES>>>();
    fwd_kernel<<<dim3(NSEG, BATCH / 2), NT, SH_BYTES>>>();
    inv_kernel<<<PCTAS, NT, SH_BYTES>>>(out);
}

// round 12
// speedup vs baseline: 1.2051x; 1.2051x over previous
#include <cuda_runtime.h>
#include <cstdint>

// ---------------- problem constants ----------------
#define BATCH    128
#define SEQLEN   16384
#define NBANDS   20
#define TAPS     513
#define PAD      512
#define EXTLEN   (SEQLEN + 2*PAD)            // 17408

// ---------------- FFT / overlap-save config ----------------
#define NFFT     4096
#define SEGSTEP  3072
#define NSEG     6
#define NPAIR    ((BATCH/2)*NSEG)            // 384
#define NT       256
#define NITEMS   (NBANDS*(BATCH/2)*NSEG)     // 7680
#define PCTAS    (148*3)                     // 444 persistent CTAs

// smem: X[4096] Y[4096] T1[256] Ta[256] float2 = 68 KB
#define SH_BYTES ((4096*2 + 512) * 8)        // 69632

// ---------------- device scratch ----------------
__device__ float2 g_spec[NPAIR * NFFT];
__device__ float  g_H[NBANDS * NFFT];

__device__ __forceinline__ int swz(int i) { return i ^ ((i >> 4) & 15); }

// ---------------------------------------------------------------------------
// FFMA-imm add/sub: x+y / x-y as fma(x, ±1.0, y) — rt_SMSP=1 (vs FADD rt 2),
// bit-exact. PTX literal prevents nvcc canonicalizing to add.f32.
// ---------------------------------------------------------------------------
__device__ __forceinline__ float fadd1(float x, float y) {
    float r; asm("fma.rn.f32 %0, %1, 0f3F800000, %2;" : "=f"(r) : "f"(x), "f"(y)); return r;
}
__device__ __forceinline__ float fsub1(float x, float y) {   // x - y
    float r; asm("fma.rn.f32 %0, %1, 0fBF800000, %2;" : "=f"(r) : "f"(y), "f"(x)); return r;
}

__device__ __forceinline__ float2 cmul(float2 a, float2 b) {
    return make_float2(fmaf(a.x, b.x, -a.y * b.y), fmaf(a.x, b.y, a.y * b.x));
}
// constant twiddle: cx, cy are compile-time literals -> FMUL/FFMA imm forms
template <bool INV>
__device__ __forceinline__ float2 cmulc(float2 a, float cx, float cy) {
    if (INV) cy = -cy;
    float m = a.y * cy;
    float n = a.y * cx;
    return make_float2(fmaf(a.x, cx, -m), fmaf(a.x, cy, n));
}

template <bool INV>
__device__ __forceinline__ void dft4(float2& x0, float2& x1, float2& x2, float2& x3) {
    float t0x = fadd1(x0.x, x2.x), t0y = fadd1(x0.y, x2.y);
    float t1x = fsub1(x0.x, x2.x), t1y = fsub1(x0.y, x2.y);
    float t2x = fadd1(x1.x, x3.x), t2y = fadd1(x1.y, x3.y);
    float t3x = fsub1(x1.x, x3.x), t3y = fsub1(x1.y, x3.y);
    x0 = make_float2(fadd1(t0x, t2x), fadd1(t0y, t2y));
    x2 = make_float2(fsub1(t0x, t2x), fsub1(t0y, t2y));
    if (!INV) {
        x1 = make_float2(fadd1(t1x, t3y), fsub1(t1y, t3x));
        x3 = make_float2(fsub1(t1x, t3y), fadd1(t1y, t3x));
    } else {
        x1 = make_float2(fsub1(t1x, t3y), fadd1(t1y, t3x));
        x3 = make_float2(fadd1(t1x, t3y), fsub1(t1y, t3x));
    }
}

#define W1X  0.92387953251128674f
#define W1Y -0.38268343236508978f
#define W2X  0.70710678118654752f
#define W2Y -0.70710678118654752f
#define W3X  0.38268343236508978f
#define W3Y -0.92387953251128674f
#define W6X -0.70710678118654752f
#define W6Y -0.70710678118654752f
#define W9X -0.92387953251128674f
#define W9Y  0.38268343236508978f

template <bool INV>
__device__ __forceinline__ void dft16(float2* a) {
    #pragma unroll
    for (int n0 = 0; n0 < 4; n0++)
        dft4<INV>(a[n0], a[n0 + 4], a[n0 + 8], a[n0 + 12]);
    a[5]  = cmulc<INV>(a[5],  W1X, W1Y);
    a[9]  = cmulc<INV>(a[9],  W2X, W2Y);
    a[13] = cmulc<INV>(a[13], W3X, W3Y);
    a[6]  = cmulc<INV>(a[6],  W2X, W2Y);
    a[10] = INV ? make_float2(-a[10].y, a[10].x) : make_float2(a[10].y, -a[10].x);
    a[14] = cmulc<INV>(a[14], W6X, W6Y);
    a[7]  = cmulc<INV>(a[7],  W3X, W3Y);
    a[11] = cmulc<INV>(a[11], W6X, W6Y);
    a[15] = cmulc<INV>(a[15], W9X, W9Y);
    #pragma unroll
    for (int k0 = 0; k0 < 4; k0++)
        dft4<INV>(a[4 * k0], a[4 * k0 + 1], a[4 * k0 + 2], a[4 * k0 + 3]);
}
#define PERM(t) ((((t) & 3) << 2) | ((t) >> 2))

// ---------------------------------------------------------------------------
// FFT-4096 (R8 structure): regs in, regs out, two smem round-trips, 2 barriers.
// Input  a[t] = x[tid + t*256]; output x[tid + t*256] = a[PERM(t)].
// ---------------------------------------------------------------------------
template <bool INV>
__device__ __forceinline__ void fft_mid(float2* a, float2* X, float2* Y,
                                        const float2* T1, const float2* Ta, int tid) {
    const int rlo = tid & 15, rhi = tid >> 4;
    // stage 0 (L=1)
    dft16<INV>(a);
    #pragma unroll
    for (int t = 0; t < 16; t++) X[swz(tid * 16 + t)] = a[PERM(t)];
    __syncthreads();
    // stage 1 (L=16)
    #pragma unroll
    for (int t = 0; t < 16; t++) a[t] = X[swz(tid + t * 256)];
    #pragma unroll
    for (int t = 1; t < 16; t++) {
        float2 w = T1[t * 16 + rlo];
        if (INV) w.y = -w.y;
        a[t] = cmul(a[t], w);
    }
    dft16<INV>(a);
    {
        int o = rhi * 256 + rlo;
        #pragma unroll
        for (int t = 0; t < 16; t++) Y[swz(o + t * 16)] = a[PERM(t)];
    }
    __syncthreads();
    // stage 2 (L=256), twiddle W^(t*tid) = Ta[t,rlo] * T1[t,rhi]
    #pragma unroll
    for (int t = 0; t < 16; t++) a[t] = Y[swz(tid + t * 256)];
    #pragma unroll
    for (int t = 1; t < 16; t++) {
        float2 wa = Ta[t * 16 + rlo];
        float2 wb = T1[t * 16 + rhi];
        if (INV) { wa.y = -wa.y; wb.y = -wb.y; }
        a[t] = cmul(a[t], cmul(wa, wb));
    }
    dft16<INV>(a);
}

// In-kernel twiddle tables (replaces setup kernel + gmem loads)
__device__ __forceinline__ void make_tables(float2* T1, float2* Ta, int tid) {
    int t = tid >> 4, r = tid & 15;
    float s_, c_;
    sincospif(2.0f * (float)(16 * t * r) / (float)NFFT, &s_, &c_);
    T1[tid] = make_float2(c_, -s_);
    sincospif(2.0f * (float)(t * r) / (float)NFFT, &s_, &c_);
    Ta[tid] = make_float2(c_, -s_);
}

// odd extension value, j in [0, EXTLEN+pad); beyond EXTLEN -> 0
__device__ __forceinline__ float extval(const float* __restrict__ xb, int j) {
    if (j < PAD)               return 2.0f * xb[0] - xb[PAD - j];
    if (j < PAD + SEQLEN)      return xb[j - PAD];
    if (j < EXTLEN) {
        int jr = j - (PAD + SEQLEN);
        return 2.0f * xb[SEQLEN - 1] - xb[SEQLEN - 2 - jr];
    }
    return 0.0f;
}

// ---------------------------------------------------------------------------
// prep: per band CTA — autocorr (from kernels) + FFT -> g_H. Tables inline.
// ---------------------------------------------------------------------------
__global__ __launch_bounds__(NT, 3) void prep_kernel(const float* __restrict__ kern) {
    extern __shared__ float2 sm[];
    float2* X = sm; float2* Y = sm + 4096; float2* T1 = sm + 8192; float2* Ta = sm + 8448;
    float* sk = (float*)X;                  // 513 floats, freed before stage-0 write
    int band = blockIdx.x, tid = threadIdx.x;
    make_tables(T1, Ta, tid);
    const float* kb = kern + band * TAPS;
    for (int i = tid; i < TAPS; i += NT) sk[i] = kb[i];
    __syncthreads();
    // a[t] = c(m) at j = tid + 256t:  m = j (j<=512) or 4096-j (j>=3584), else 0
    float2 a[16];
    #pragma unroll
    for (int t = 0; t < 16; t++) {
        int j = tid + t * 256;
        int m = (j <= PAD) ? j : ((j >= NFFT - PAD) ? NFFT - j : -1);
        float s = 0.0f;
        if (m >= 0) {
            for (int j2 = 0; j2 + m < TAPS; j2++) s = fmaf(sk[j2], sk[j2 + m], s);
        }
        a[t] = make_float2(s, 0.0f);
    }
    __syncthreads();                        // sk reads done before X reuse
    fft_mid<false>(a, X, Y, T1, Ta, tid);
    const float invn = 1.0f / (float)NFFT;
    #pragma unroll
    for (int t = 0; t < 16; t++)
        g_H[band * NFFT + tid + t * 256] = a[PERM(t)].x * invn;
}

// ---------------------------------------------------------------------------
// forward: odd extension computed inline from x; z = ext(2bp) + i*ext(2bp+1)
// ---------------------------------------------------------------------------
__global__ __launch_bounds__(NT, 3) void fwd_kernel(const float* __restrict__ x) {
    extern __shared__ float2 sm[];
    float2* X = sm; float2* Y = sm + 4096; float2* T1 = sm + 8192; float2* Ta = sm + 8448;
    int s = blockIdx.x, bp = blockIdx.y, tid = threadIdx.x;
    make_tables(T1, Ta, tid);
    const float* xa = x + (size_t)(2 * bp) * SEQLEN;
    const float* xb = xa + SEQLEN;
    int j0 = s * SEGSTEP + tid;
    float2 a[16];
    #pragma unroll
    for (int t = 0; t < 16; t++) {
        int j = j0 + t * 256;
        a[t] = make_float2(extval(xa, j), extval(xb, j));
    }
    __syncthreads();                        // tables ready
    fft_mid<false>(a, X, Y, T1, Ta, tid);
    float2* sp = g_spec + (size_t)(bp * NSEG + s) * NFFT;
    #pragma unroll
    for (int t = 0; t < 16; t++)
        sp[tid + t * 256] = a[PERM(t)];
}

// ---------------------------------------------------------------------------
// inverse: persistent CTAs (R8 structure: Z,H gmem->regs, direct reg->gmem out)
// ---------------------------------------------------------------------------
__global__ __launch_bounds__(NT, 3) void inv_kernel(float* __restrict__ out) {
    extern __shared__ float2 sm[];
    float2* X = sm; float2* Y = sm + 4096; float2* T1 = sm + 8192; float2* Ta = sm + 8448;
    int tid = threadIdx.x;
    make_tables(T1, Ta, tid);
    __syncthreads();
    for (int item = blockIdx.x; item < NITEMS; item += PCTAS) {
        int band = item / (NSEG * (BATCH / 2));
        int rem  = item - band * NSEG * (BATCH / 2);
        int bp   = rem / NSEG;
        int s    = rem - bp * NSEG;
        const float2* sp = g_spec + (size_t)(bp * NSEG + s) * NFFT;
        const float*  Hb = g_H + (size_t)band * NFFT;
        float h[16];
        #pragma unroll
        for (int t = 0; t < 16; t++) h[t] = Hb[tid + t * 256];
        float2 a[16];
        #pragma unroll
        for (int t = 0; t < 16; t++) {
            float2 z = sp[tid + t * 256];
            a[t] = make_float2(z.x * h[t], z.y * h[t]);
        }
        fft_mid<true>(a, X, Y, T1, Ta, tid);
        // output: j = tid + t*256, valid t = 2..13
        size_t basea = ((size_t)(2 * bp) * NBANDS + band) * SEQLEN;
        size_t baseb = basea + (size_t)NBANDS * SEQLEN;
        int pos0 = s * SEGSTEP - PAD + tid;
        #pragma unroll
        for (int t = 2; t <= 13; t++) {
            int pos = pos0 + t * 256;
            if (pos < SEQLEN) {
                float2 y = a[PERM(t)];
                out[basea + pos] = y.x;
                out[baseb + pos] = y.y;
            }
        }
        // next item's first barrier orders X/Y reuse (proven in R8)
    }
}

// ---------------------------------------------------------------------------
extern "C" void kernel_launch(void* const* d_in, const int* in_sizes, int n_in,
                              void* d_out, int out_size) {
    (void)in_sizes; (void)n_in; (void)out_size;
    const float* x    = (const float*)d_in[0];
    const float* kern = (const float*)d_in[1];
    float* out = (float*)d_out;

    cudaFuncSetAttribute(prep_kernel, cudaFuncAttributeMaxDynamicSharedMemorySize, SH_BYTES);
    cudaFuncSetAttribute(fwd_kernel,  cudaFuncAttributeMaxDynamicSharedMemorySize, SH_BYTES);
    cudaFuncSetAttribute(inv_kernel,  cudaFuncAttributeMaxDynamicSharedMemorySize, SH_BYTES);

    prep_kernel<<<NBANDS, NT, SH_BYTES>>>(kern);
    fwd_kernel<<<dim3(NSEG, BATCH / 2), NT, SH_BYTES>>>(x);
    inv_kernel<<<PCTAS, NT, SH_BYTES>>>(out);
}

// round 13
// speedup vs baseline: 1.2394x; 1.0284x over previous
#include <cuda_runtime.h>
#include <cstdint>

// ---------------- problem constants ----------------
#define BATCH    128
#define SEQLEN   16384
#define NBANDS   20
#define TAPS     513
#define PAD      512
#define EXTLEN   (SEQLEN + 2*PAD)            // 17408

// ---------------- FFT / overlap-save config ----------------
#define NFFT     4096
#define SEGSTEP  3072
#define NSEG     6
#define NPAIR    ((BATCH/2)*NSEG)            // 384
#define NT       256
#define NITEMS   (NBANDS*(BATCH/2)*NSEG)     // 7680
#define PCTAS    (148*3)                     // 444 persistent CTAs

// smem: X[4096] Y[4096] T1[256] Ta[256] float2 = 68 KB
#define SH_BYTES ((4096*2 + 512) * 8)        // 69632

// ---------------- device scratch ----------------
__device__ float2 g_spec[NPAIR * NFFT];
__device__ float  g_H[NBANDS * NFFT];

__device__ __forceinline__ int swz(int i) { return i ^ ((i >> 4) & 15); }

// FFMA-imm add/sub: x+y / x-y as fma(x, ±1.0, y) — rt_SMSP=1, bit-exact.
__device__ __forceinline__ float fadd1(float x, float y) {
    float r; asm("fma.rn.f32 %0, %1, 0f3F800000, %2;" : "=f"(r) : "f"(x), "f"(y)); return r;
}
__device__ __forceinline__ float fsub1(float x, float y) {   // x - y
    float r; asm("fma.rn.f32 %0, %1, 0fBF800000, %2;" : "=f"(r) : "f"(y), "f"(x)); return r;
}

__device__ __forceinline__ float2 cmul(float2 a, float2 b) {
    return make_float2(fmaf(a.x, b.x, -a.y * b.y), fmaf(a.x, b.y, a.y * b.x));
}
template <bool INV>
__device__ __forceinline__ float2 cmulc(float2 a, float cx, float cy) {
    if (INV) cy = -cy;
    float m = a.y * cy;
    float n = a.y * cx;
    return make_float2(fmaf(a.x, cx, -m), fmaf(a.x, cy, n));
}

template <bool INV>
__device__ __forceinline__ void dft4(float2& x0, float2& x1, float2& x2, float2& x3) {
    float t0x = fadd1(x0.x, x2.x), t0y = fadd1(x0.y, x2.y);
    float t1x = fsub1(x0.x, x2.x), t1y = fsub1(x0.y, x2.y);
    float t2x = fadd1(x1.x, x3.x), t2y = fadd1(x1.y, x3.y);
    float t3x = fsub1(x1.x, x3.x), t3y = fsub1(x1.y, x3.y);
    x0 = make_float2(fadd1(t0x, t2x), fadd1(t0y, t2y));
    x2 = make_float2(fsub1(t0x, t2x), fsub1(t0y, t2y));
    if (!INV) {
        x1 = make_float2(fadd1(t1x, t3y), fsub1(t1y, t3x));
        x3 = make_float2(fsub1(t1x, t3y), fadd1(t1y, t3x));
    } else {
        x1 = make_float2(fsub1(t1x, t3y), fadd1(t1y, t3x));
        x3 = make_float2(fadd1(t1x, t3y), fsub1(t1y, t3x));
    }
}

#define W1X  0.92387953251128674f
#define W1Y -0.38268343236508978f
#define W2X  0.70710678118654752f
#define W2Y -0.70710678118654752f
#define W3X  0.38268343236508978f
#define W3Y -0.92387953251128674f
#define W6X -0.70710678118654752f
#define W6Y -0.70710678118654752f
#define W9X -0.92387953251128674f
#define W9Y  0.38268343236508978f

template <bool INV>
__device__ __forceinline__ void dft16(float2* a) {
    #pragma unroll
    for (int n0 = 0; n0 < 4; n0++)
        dft4<INV>(a[n0], a[n0 + 4], a[n0 + 8], a[n0 + 12]);
    a[5]  = cmulc<INV>(a[5],  W1X, W1Y);
    a[9]  = cmulc<INV>(a[9],  W2X, W2Y);
    a[13] = cmulc<INV>(a[13], W3X, W3Y);
    a[6]  = cmulc<INV>(a[6],  W2X, W2Y);
    a[10] = INV ? make_float2(-a[10].y, a[10].x) : make_float2(a[10].y, -a[10].x);
    a[14] = cmulc<INV>(a[14], W6X, W6Y);
    a[7]  = cmulc<INV>(a[7],  W3X, W3Y);
    a[11] = cmulc<INV>(a[11], W6X, W6Y);
    a[15] = cmulc<INV>(a[15], W9X, W9Y);
    #pragma unroll
    for (int k0 = 0; k0 < 4; k0++)
        dft4<INV>(a[4 * k0], a[4 * k0 + 1], a[4 * k0 + 2], a[4 * k0 + 3]);
}
#define PERM(t) ((((t) & 3) << 2) | ((t) >> 2))

// ---------------------------------------------------------------------------
// FFT-4096: regs in, regs out, two smem round-trips, 2 barriers.
// Input  a[t] = x[tid + t*256]; output x[tid + t*256] = a[PERM(t)].
// ---------------------------------------------------------------------------
template <bool INV>
__device__ __forceinline__ void fft_mid(float2* a, float2* X, float2* Y,
                                        const float2* T1, const float2* Ta, int tid) {
    const int rlo = tid & 15, rhi = tid >> 4;
    dft16<INV>(a);
    #pragma unroll
    for (int t = 0; t < 16; t++) X[swz(tid * 16 + t)] = a[PERM(t)];
    __syncthreads();
    #pragma unroll
    for (int t = 0; t < 16; t++) a[t] = X[swz(tid + t * 256)];
    #pragma unroll
    for (int t = 1; t < 16; t++) {
        float2 w = T1[t * 16 + rlo];
        if (INV) w.y = -w.y;
        a[t] = cmul(a[t], w);
    }
    dft16<INV>(a);
    {
        int o = rhi * 256 + rlo;
        #pragma unroll
        for (int t = 0; t < 16; t++) Y[swz(o + t * 16)] = a[PERM(t)];
    }
    __syncthreads();
    #pragma unroll
    for (int t = 0; t < 16; t++) a[t] = Y[swz(tid + t * 256)];
    #pragma unroll
    for (int t = 1; t < 16; t++) {
        float2 wa = Ta[t * 16 + rlo];
        float2 wb = T1[t * 16 + rhi];
        if (INV) { wa.y = -wa.y; wb.y = -wb.y; }
        a[t] = cmul(a[t], cmul(wa, wb));
    }
    dft16<INV>(a);
}

__device__ __forceinline__ void make_tables(float2* T1, float2* Ta, int tid) {
    int t = tid >> 4, r = tid & 15;
    float s_, c_;
    sincospif(2.0f * (float)(16 * t * r) / (float)NFFT, &s_, &c_);
    T1[tid] = make_float2(c_, -s_);
    sincospif(2.0f * (float)(t * r) / (float)NFFT, &s_, &c_);
    Ta[tid] = make_float2(c_, -s_);
}

__device__ __forceinline__ float extval(const float* __restrict__ xb, int j) {
    if (j < PAD)               return 2.0f * xb[0] - xb[PAD - j];
    if (j < PAD + SEQLEN)      return xb[j - PAD];
    if (j < EXTLEN) {
        int jr = j - (PAD + SEQLEN);
        return 2.0f * xb[SEQLEN - 1] - xb[SEQLEN - 2 - jr];
    }
    return 0.0f;
}

__device__ __forceinline__ void stcs(float* p, float v) {
    asm volatile("st.global.cs.f32 [%0], %1;" :: "l"(p), "f"(v) : "memory");
}

// ---------------------------------------------------------------------------
// fused forward + prep: every CTA does one segment FFT -> g_spec; the first
// NBANDS CTAs (linear id < 20) additionally compute their band's H -> g_H.
// ---------------------------------------------------------------------------
__global__ __launch_bounds__(NT, 3) void fwd_kernel(const float* __restrict__ x,
                                                    const float* __restrict__ kern) {
    extern __shared__ float2 sm[];
    float2* X = sm; float2* Y = sm + 4096; float2* T1 = sm + 8192; float2* Ta = sm + 8448;
    int s = blockIdx.x, bp = blockIdx.y, tid = threadIdx.x;
    int cta = bp * NSEG + s;
    make_tables(T1, Ta, tid);
    const float* xa = x + (size_t)(2 * bp) * SEQLEN;
    const float* xb = xa + SEQLEN;
    int j0 = s * SEGSTEP + tid;
    float2 a[16];
    #pragma unroll
    for (int t = 0; t < 16; t++) {
        int j = j0 + t * 256;
        a[t] = make_float2(extval(xa, j), extval(xb, j));
    }
    __syncthreads();                        // tables ready
    fft_mid<false>(a, X, Y, T1, Ta, tid);
    float2* sp = g_spec + (size_t)cta * NFFT;
    #pragma unroll
    for (int t = 0; t < 16; t++)
        sp[tid + t * 256] = a[PERM(t)];

    // ---- prep path: band = cta for cta < NBANDS ----
    if (cta < NBANDS) {
        __syncthreads();                    // X/Y free (all spec stores issued)
        float* sk = (float*)X;              // 513 floats
        const float* kb = kern + cta * TAPS;
        for (int i = tid; i < TAPS; i += NT) sk[i] = kb[i];
        __syncthreads();
        // c(m) with 4 independent accumulators (break the FMA chain)
        #pragma unroll
        for (int t = 0; t < 16; t++) {
            int j = tid + t * 256;
            int m = (j <= PAD) ? j : ((j >= NFFT - PAD) ? NFFT - j : -1);
            float s0 = 0.0f, s1 = 0.0f, s2 = 0.0f, s3 = 0.0f;
            if (m >= 0) {
                int len = TAPS - m;         // 1..513
                int j2 = 0;
                for (; j2 + 3 < len; j2 += 4) {
                    s0 = fmaf(sk[j2],     sk[j2 + m],     s0);
                    s1 = fmaf(sk[j2 + 1], sk[j2 + 1 + m], s1);
                    s2 = fmaf(sk[j2 + 2], sk[j2 + 2 + m], s2);
                    s3 = fmaf(sk[j2 + 3], sk[j2 + 3 + m], s3);
                }
                for (; j2 < len; j2++) s0 = fmaf(sk[j2], sk[j2 + m], s0);
            }
            a[t] = make_float2((s0 + s1) + (s2 + s3), 0.0f);
        }
        __syncthreads();                    // sk reads done before X reuse
        fft_mid<false>(a, X, Y, T1, Ta, tid);
        const float invn = 1.0f / (float)NFFT;
        #pragma unroll
        for (int t = 0; t < 16; t++)
            g_H[cta * NFFT + tid + t * 256] = a[PERM(t)].x * invn;
    }
}

// ---------------------------------------------------------------------------
// inverse: persistent CTAs; Z,H gmem->regs, FFT, direct reg->gmem (.cs) out
// ---------------------------------------------------------------------------
__global__ __launch_bounds__(NT, 3) void inv_kernel(float* __restrict__ out) {
    extern __shared__ float2 sm[];
    float2* X = sm; float2* Y = sm + 4096; float2* T1 = sm + 8192; float2* Ta = sm + 8448;
    int tid = threadIdx.x;
    make_tables(T1, Ta, tid);
    __syncthreads();
    for (int item = blockIdx.x; item < NITEMS; item += PCTAS) {
        int band = item / (NSEG * (BATCH / 2));
        int rem  = item - band * NSEG * (BATCH / 2);
        int bp   = rem / NSEG;
        int s    = rem - bp * NSEG;
        const float2* sp = g_spec + (size_t)(bp * NSEG + s) * NFFT;
        const float*  Hb = g_H + (size_t)band * NFFT;
        float h[16];
        #pragma unroll
        for (int t = 0; t < 16; t++) h[t] = Hb[tid + t * 256];
        float2 a[16];
        #pragma unroll
        for (int t = 0; t < 16; t++) {
            float2 z = sp[tid + t * 256];
            a[t] = make_float2(z.x * h[t], z.y * h[t]);
        }
        fft_mid<true>(a, X, Y, T1, Ta, tid);
        size_t basea = ((size_t)(2 * bp) * NBANDS + band) * SEQLEN;
        size_t baseb = basea + (size_t)NBANDS * SEQLEN;
        int pos0 = s * SEGSTEP - PAD + tid;
        #pragma unroll
        for (int t = 2; t <= 13; t++) {
            int pos = pos0 + t * 256;
            if (pos < SEQLEN) {
                float2 y = a[PERM(t)];
                stcs(out + basea + pos, y.x);
                stcs(out + baseb + pos, y.y);
            }
        }
    }
}

// ---------------------------------------------------------------------------
extern "C" void kernel_launch(void* const* d_in, const int* in_sizes, int n_in,
                              void* d_out, int out_size) {
    (void)in_sizes; (void)n_in; (void)out_size;
    const float* x    = (const float*)d_in[0];
    const float* kern = (const float*)d_in[1];
    float* out = (float*)d_out;

    cudaFuncSetAttribute(fwd_kernel, cudaFuncAttributeMaxDynamicSharedMemorySize, SH_BYTES);
    cudaFuncSetAttribute(inv_kernel, cudaFuncAttributeMaxDynamicSharedMemorySize, SH_BYTES);

    fwd_kernel<<<dim3(NSEG, BATCH / 2), NT, SH_BYTES>>>(x, kern);
    inv_kernel<<<PCTAS, NT, SH_BYTES>>>(out);
}

// round 15
// speedup vs baseline: 1.2571x; 1.0143x over previous
#include <cuda_runtime.h>
#include <cstdint>

// ---------------- problem constants ----------------
#define BATCH    128
#define SEQLEN   16384
#define NBANDS   20
#define TAPS     513
#define PAD      512
#define EXTLEN   (SEQLEN + 2*PAD)            // 17408

// ---------------- FFT / overlap-save config ----------------
#define NFFT     4096
#define SEGSTEP  3072
#define NSEG     6
#define NPAIR    ((BATCH/2)*NSEG)            // 384
#define NT       256
#define NITEMS   (NBANDS*(BATCH/2)*NSEG)     // 7680
#define PCTAS    (148*4)                     // 592 persistent CTAs (4/SM)

// fwd smem: X[4096] Y[4096] T1[256] Ta[256] float2 = 68 KB
#define FWD_SH   ((4096*2 + 512) * 8)        // 69632
// inv smem: X[4096] T1[256] Ta[256] float2 = 36 KB
#define INV_SH   ((4096 + 512) * 8)          // 36864

// ---------------- device scratch ----------------
__device__ float2 g_spec[NPAIR * NFFT];
__device__ float  g_H[NBANDS * NFFT];

__device__ __forceinline__ int swz(int i) { return i ^ ((i >> 4) & 15); }

// FFMA-imm add/sub: x+y / x-y as fma(x, ±1.0, y) — rt_SMSP=1, bit-exact.
__device__ __forceinline__ float fadd1(float x, float y) {
    float r; asm("fma.rn.f32 %0, %1, 0f3F800000, %2;" : "=f"(r) : "f"(x), "f"(y)); return r;
}
__device__ __forceinline__ float fsub1(float x, float y) {   // x - y
    float r; asm("fma.rn.f32 %0, %1, 0fBF800000, %2;" : "=f"(r) : "f"(y), "f"(x)); return r;
}

__device__ __forceinline__ float2 cmul(float2 a, float2 b) {
    return make_float2(fmaf(a.x, b.x, -a.y * b.y), fmaf(a.x, b.y, a.y * b.x));
}
template <bool INV>
__device__ __forceinline__ float2 cmulc(float2 a, float cx, float cy) {
    if (INV) cy = -cy;
    float m = a.y * cy;
    float n = a.y * cx;
    return make_float2(fmaf(a.x, cx, -m), fmaf(a.x, cy, n));
}

template <bool INV>
__device__ __forceinline__ void dft4(float2& x0, float2& x1, float2& x2, float2& x3) {
    float t0x = fadd1(x0.x, x2.x), t0y = fadd1(x0.y, x2.y);
    float t1x = fsub1(x0.x, x2.x), t1y = fsub1(x0.y, x2.y);
    float t2x = fadd1(x1.x, x3.x), t2y = fadd1(x1.y, x3.y);
    float t3x = fsub1(x1.x, x3.x), t3y = fsub1(x1.y, x3.y);
    x0 = make_float2(fadd1(t0x, t2x), fadd1(t0y, t2y));
    x2 = make_float2(fsub1(t0x, t2x), fsub1(t0y, t2y));
    if (!INV) {
        x1 = make_float2(fadd1(t1x, t3y), fsub1(t1y, t3x));
        x3 = make_float2(fsub1(t1x, t3y), fadd1(t1y, t3x));
    } else {
        x1 = make_float2(fsub1(t1x, t3y), fadd1(t1y, t3x));
        x3 = make_float2(fadd1(t1x, t3y), fsub1(t1y, t3x));
    }
}

#define W1X  0.92387953251128674f
#define W1Y -0.38268343236508978f
#define W2X  0.70710678118654752f
#define W2Y -0.70710678118654752f
#define W3X  0.38268343236508978f
#define W3Y -0.92387953251128674f
#define W6X -0.70710678118654752f
#define W6Y -0.70710678118654752f
#define W9X -0.92387953251128674f
#define W9Y  0.38268343236508978f

template <bool INV>
__device__ __forceinline__ void dft16(float2* a) {
    #pragma unroll
    for (int n0 = 0; n0 < 4; n0++)
        dft4<INV>(a[n0], a[n0 + 4], a[n0 + 8], a[n0 + 12]);
    a[5]  = cmulc<INV>(a[5],  W1X, W1Y);
    a[9]  = cmulc<INV>(a[9],  W2X, W2Y);
    a[13] = cmulc<INV>(a[13], W3X, W3Y);
    a[6]  = cmulc<INV>(a[6],  W2X, W2Y);
    a[10] = INV ? make_float2(-a[10].y, a[10].x) : make_float2(a[10].y, -a[10].x);
    a[14] = cmulc<INV>(a[14], W6X, W6Y);
    a[7]  = cmulc<INV>(a[7],  W3X, W3Y);
    a[11] = cmulc<INV>(a[11], W6X, W6Y);
    a[15] = cmulc<INV>(a[15], W9X, W9Y);
    #pragma unroll
    for (int k0 = 0; k0 < 4; k0++)
        dft4<INV>(a[4 * k0], a[4 * k0 + 1], a[4 * k0 + 2], a[4 * k0 + 3]);
}
#define PERM(t) ((((t) & 3) << 2) | ((t) >> 2))

// ---------------------------------------------------------------------------
// Two-buffer FFT (fwd/prep): 2 barriers.
// ---------------------------------------------------------------------------
template <bool INV>
__device__ __forceinline__ void fft_mid(float2* a, float2* X, float2* Y,
                                        const float2* T1, const float2* Ta, int tid) {
    const int rlo = tid & 15, rhi = tid >> 4;
    dft16<INV>(a);
    #pragma unroll
    for (int t = 0; t < 16; t++) X[swz(tid * 16 + t)] = a[PERM(t)];
    __syncthreads();
    #pragma unroll
    for (int t = 0; t < 16; t++) a[t] = X[swz(tid + t * 256)];
    #pragma unroll
    for (int t = 1; t < 16; t++) {
        float2 w = T1[t * 16 + rlo];
        if (INV) w.y = -w.y;
        a[t] = cmul(a[t], w);
    }
    dft16<INV>(a);
    {
        int o = rhi * 256 + rlo;
        #pragma unroll
        for (int t = 0; t < 16; t++) Y[swz(o + t * 16)] = a[PERM(t)];
    }
    __syncthreads();
    #pragma unroll
    for (int t = 0; t < 16; t++) a[t] = Y[swz(tid + t * 256)];
    #pragma unroll
    for (int t = 1; t < 16; t++) {
        float2 wa = Ta[t * 16 + rlo];
        float2 wb = T1[t * 16 + rhi];
        if (INV) { wa.y = -wa.y; wb.y = -wb.y; }
        a[t] = cmul(a[t], cmul(wa, wb));
    }
    dft16<INV>(a);
}

// ---------------------------------------------------------------------------
// In-place FFT (inverse): single X buffer, 3 internal barriers.
// Caller supplies a trailing __syncthreads() before X is rewritten.
// ---------------------------------------------------------------------------
template <bool INV>
__device__ __forceinline__ void fft_ip(float2* a, float2* X,
                                       const float2* T1, const float2* Ta, int tid) {
    const int rlo = tid & 15, rhi = tid >> 4;
    dft16<INV>(a);
    #pragma unroll
    for (int t = 0; t < 16; t++) X[swz(tid * 16 + t)] = a[PERM(t)];
    __syncthreads();
    #pragma unroll
    for (int t = 0; t < 16; t++) a[t] = X[swz(tid + t * 256)];
    __syncthreads();                        // all reads before in-place writes
    #pragma unroll
    for (int t = 1; t < 16; t++) {
        float2 w = T1[t * 16 + rlo];
        if (INV) w.y = -w.y;
        a[t] = cmul(a[t], w);
    }
    dft16<INV>(a);
    {
        int o = rhi * 256 + rlo;
        #pragma unroll
        for (int t = 0; t < 16; t++) X[swz(o + t * 16)] = a[PERM(t)];
    }
    __syncthreads();
    #pragma unroll
    for (int t = 0; t < 16; t++) a[t] = X[swz(tid + t * 256)];
    #pragma unroll
    for (int t = 1; t < 16; t++) {
        float2 wa = Ta[t * 16 + rlo];
        float2 wb = T1[t * 16 + rhi];
        if (INV) { wa.y = -wa.y; wb.y = -wb.y; }
        a[t] = cmul(a[t], cmul(wa, wb));
    }
    dft16<INV>(a);
}

__device__ __forceinline__ void make_tables(float2* T1, float2* Ta, int tid) {
    int t = tid >> 4, r = tid & 15;
    float s_, c_;
    sincospif(2.0f * (float)(16 * t * r) / (float)NFFT, &s_, &c_);
    T1[tid] = make_float2(c_, -s_);
    sincospif(2.0f * (float)(t * r) / (float)NFFT, &s_, &c_);
    Ta[tid] = make_float2(c_, -s_);
}

__device__ __forceinline__ float extval(const float* __restrict__ xb, int j) {
    if (j < PAD)               return 2.0f * xb[0] - xb[PAD - j];
    if (j < PAD + SEQLEN)      return xb[j - PAD];
    if (j < EXTLEN) {
        int jr = j - (PAD + SEQLEN);
        return 2.0f * xb[SEQLEN - 1] - xb[SEQLEN - 2 - jr];
    }
    return 0.0f;
}

__device__ __forceinline__ void stcs(float* p, float v) {
    asm volatile("st.global.cs.f32 [%0], %1;" :: "l"(p), "f"(v) : "memory");
}

// ---------------------------------------------------------------------------
// fused forward + prep (unchanged from R13)
// ---------------------------------------------------------------------------
__global__ __launch_bounds__(NT, 3) void fwd_kernel(const float* __restrict__ x,
                                                    const float* __restrict__ kern) {
    extern __shared__ float2 sm[];
    float2* X = sm; float2* Y = sm + 4096; float2* T1 = sm + 8192; float2* Ta = sm + 8448;
    int s = blockIdx.x, bp = blockIdx.y, tid = threadIdx.x;
    int cta = bp * NSEG + s;
    make_tables(T1, Ta, tid);
    const float* xa = x + (size_t)(2 * bp) * SEQLEN;
    const float* xb = xa + SEQLEN;
    int j0 = s * SEGSTEP + tid;
    float2 a[16];
    #pragma unroll
    for (int t = 0; t < 16; t++) {
        int j = j0 + t * 256;
        a[t] = make_float2(extval(xa, j), extval(xb, j));
    }
    __syncthreads();                        // tables ready
    fft_mid<false>(a, X, Y, T1, Ta, tid);
    float2* sp = g_spec + (size_t)cta * NFFT;
    #pragma unroll
    for (int t = 0; t < 16; t++)
        sp[tid + t * 256] = a[PERM(t)];

    if (cta < NBANDS) {
        __syncthreads();
        float* sk = (float*)X;
        const float* kb = kern + cta * TAPS;
        for (int i = tid; i < TAPS; i += NT) sk[i] = kb[i];
        __syncthreads();
        #pragma unroll
        for (int t = 0; t < 16; t++) {
            int j = tid + t * 256;
            int m = (j <= PAD) ? j : ((j >= NFFT - PAD) ? NFFT - j : -1);
            float s0 = 0.0f, s1 = 0.0f, s2 = 0.0f, s3 = 0.0f;
            if (m >= 0) {
                int len = TAPS - m;
                int j2 = 0;
                for (; j2 + 3 < len; j2 += 4) {
                    s0 = fmaf(sk[j2],     sk[j2 + m],     s0);
                    s1 = fmaf(sk[j2 + 1], sk[j2 + 1 + m], s1);
                    s2 = fmaf(sk[j2 + 2], sk[j2 + 2 + m], s2);
                    s3 = fmaf(sk[j2 + 3], sk[j2 + 3 + m], s3);
                }
                for (; j2 < len; j2++) s0 = fmaf(sk[j2], sk[j2 + m], s0);
            }
            a[t] = make_float2((s0 + s1) + (s2 + s3), 0.0f);
        }
        __syncthreads();
        fft_mid<false>(a, X, Y, T1, Ta, tid);
        const float invn = 1.0f / (float)NFFT;
        #pragma unroll
        for (int t = 0; t < 16; t++)
            g_H[cta * NFFT + tid + t * 256] = a[PERM(t)].x * invn;
    }
}

// ---------------------------------------------------------------------------
// inverse: 4 CTAs/SM, in-place FFT, interleaved H*Z load-multiply
// ---------------------------------------------------------------------------
__global__ __launch_bounds__(NT, 4) void inv_kernel(float* __restrict__ out) {
    extern __shared__ float2 sm[];
    float2* X = sm; float2* T1 = sm + 4096; float2* Ta = sm + 4352;
    int tid = threadIdx.x;
    make_tables(T1, Ta, tid);
    __syncthreads();
    for (int item = blockIdx.x; item < NITEMS; item += PCTAS) {
        int band = item / (NSEG * (BATCH / 2));
        int rem  = item - band * NSEG * (BATCH / 2);
        int bp   = rem / NSEG;
        int s    = rem - bp * NSEG;
        const float2* sp = g_spec + (size_t)(bp * NSEG + s) * NFFT;
        const float*  Hb = g_H + (size_t)band * NFFT;
        float2 a[16];
        #pragma unroll
        for (int t = 0; t < 16; t++) {
            float  h = Hb[tid + t * 256];
            float2 z = sp[tid + t * 256];
            a[t] = make_float2(z.x * h, z.y * h);
        }
        fft_ip<true>(a, X, T1, Ta, tid);
        size_t basea = ((size_t)(2 * bp) * NBANDS + band) * SEQLEN;
        size_t baseb = basea + (size_t)NBANDS * SEQLEN;
        int pos0 = s * SEGSTEP - PAD + tid;
        #pragma unroll
        for (int t = 2; t <= 13; t++) {
            int pos = pos0 + t * 256;
            if (pos < SEQLEN) {
                float2 y = a[PERM(t)];
                stcs(out + basea + pos, y.x);
                stcs(out + baseb + pos, y.y);
            }
        }
        __syncthreads();   // X reads of this item done before next item writes X
    }
}

// ---------------------------------------------------------------------------
extern "C" void kernel_launch(void* const* d_in, const int* in_sizes, int n_in,
                              void* d_out, int out_size) {
    (void)in_sizes; (void)n_in; (void)out_size;
    const float* x    = (const float*)d_in[0];
    const float* kern = (const float*)d_in[1];
    float* out = (float*)d_out;

    cudaFuncSetAttribute(fwd_kernel, cudaFuncAttributeMaxDynamicSharedMemorySize, FWD_SH);
    cudaFuncSetAttribute(inv_kernel, cudaFuncAttributeMaxDynamicSharedMemorySize, INV_SH);

    fwd_kernel<<<dim3(NSEG, BATCH / 2), NT, FWD_SH>>>(x, kern);
    inv_kernel<<<PCTAS, NT, INV_SH>>>(out);
}